// round 1
// baseline (speedup 1.0000x reference)
#include <cuda_runtime.h>
#include <cstdint>

#define RES0 2048
#define RES1 1024
#define NPTS 2097152

// Packed 4-bit code tables. Each u64 entry at (y,x) holds:
//   low 32 bits  : 8 channel nibbles of texel (y,x)
//   high 32 bits : 8 channel nibbles of texel (y,min(x+1,RES-1))
// g0 table: 32 MB, g1 table: 8 MB -> both L2-resident (126 MB L2).
__device__ uint64_t g_tab0[(size_t)RES0 * RES0];
__device__ uint64_t g_tab1[(size_t)RES1 * RES1];

// codes = clip(round((v - lo)/q), 0, 15) with lo=-15/32, q=1/16.
// Matches reference op order: (v - lo) rounded, then exact *16 scaling.
// __float2int_rn = round-half-to-even, matching jnp.round.
__device__ __forceinline__ uint32_t quant_code(float v) {
    float t = __fmul_rn(__fadd_rn(v, 0.46875f), 16.0f);
    int c = __float2int_rn(t);
    c = max(0, min(15, c));
    return (uint32_t)c;
}

// Exact dequant of nibble i: c/16 - 15/32.
// (1 + c/16) is exactly 0x3F800000 | (c<<19); subtracting 1.46875 is exact.
__device__ __forceinline__ float dec(uint32_t p, int i) {
    uint32_t u = 0x3F800000u | (((p >> (4 * i)) & 0xFu) << 19);
    return __uint_as_float(u) - 1.46875f;
}

template <int RES>
__global__ __launch_bounds__(256) void pack_kernel(const float* __restrict__ g,
                                                   uint64_t* __restrict__ tab) {
    int idx = blockIdx.x * 256 + threadIdx.x;  // y*RES + x
    if (idx >= RES * RES) return;
    int x = idx & (RES - 1);
    int xn = min(x + 1, RES - 1);
    int base = idx - x;  // y*RES

    uint32_t p0 = 0, p1 = 0;
#pragma unroll
    for (int c = 0; c < 8; c++) {
        float v0 = g[(size_t)c * RES * RES + idx];
        float v1 = g[(size_t)c * RES * RES + base + xn];  // adjacent -> cache hit
        p0 |= quant_code(v0) << (4 * c);
        p1 |= quant_code(v1) << (4 * c);
    }
    tab[idx] = (uint64_t)p0 | ((uint64_t)p1 << 32);
}

__global__ __launch_bounds__(256) void sample_kernel(const float2* __restrict__ uv,
                                                     float* __restrict__ out) {
    // Per-warp staging: 32 points x 44-word stride (40 data + 4 pad).
    // Stride 44 -> STS.128 conflict-free, 16B-aligned groups.
    __shared__ __align__(16) float sbuf[8 * 32 * 44];

    int tid = threadIdx.x;
    int lane = tid & 31;
    int warp = tid >> 5;
    int i = blockIdx.x * 256 + tid;

    float2 p = uv[i];

    // ---------------- feat0: 4-corner gather on g0 (no interpolation) -------
    // pos = uv*2048 - 0.5 ; x0 = clip(floor(pos), 0, 2046)
    float px = fmaf(p.x, 2048.0f, -0.5f);   // u*2048 exact -> identical to (u*2048)-0.5
    float py = fmaf(p.y, 2048.0f, -0.5f);
    int x0 = min(max((int)floorf(px), 0), RES0 - 2);
    int y0 = min(max((int)floorf(py), 0), RES0 - 2);

    const uint64_t* r0 = g_tab0 + (size_t)y0 * RES0 + x0;
    uint64_t e_top = r0[0];        // (x0, x1) at y0
    uint64_t e_bot = r0[RES0];     // (x0, x1) at y1

    // ---------------- feat1: bilinear grid_sample on g1 ---------------------
    // ix = ((u*2-1)+1)*0.5*1024 - 0.5 == u*1024 - 0.5 (exact: u*1024 is exact)
    float ix = fmaf(p.x, 1024.0f, -0.5f);
    float iy = fmaf(p.y, 1024.0f, -0.5f);
    float fx0 = floorf(ix), fy0 = floorf(iy);
    float wx1 = __fsub_rn(ix, fx0), wx0 = __fsub_rn(1.0f, wx1);
    float wy1 = __fsub_rn(iy, fy0), wy0 = __fsub_rn(1.0f, wy1);
    int qx0 = (int)fx0;  // in [-1, 1023]
    int qy0 = (int)fy0;

    bool vx0 = (qx0 >= 0);
    bool vx1 = (qx0 + 1 <= RES1 - 1);
    bool vy0 = (qy0 >= 0);
    bool vy1 = (qy0 + 1 <= RES1 - 1);

    float wx0m = vx0 ? wx0 : 0.0f;
    float wx1m = vx1 ? wx1 : 0.0f;
    float wy0m = vy0 ? wy0 : 0.0f;
    float wy1m = vy1 ? wy1 : 0.0f;

    int cx  = max(qx0, 0);
    int cy0 = max(qy0, 0);
    int cy1 = min(qy0 + 1, RES1 - 1);

    uint64_t et = g_tab1[(size_t)cy0 * RES1 + cx];
    uint64_t eb = g_tab1[(size_t)cy1 * RES1 + cx];

    // Decode g0 corners: order plane[y0,x0], plane[y0,x1], plane[y1,x0], plane[y1,x1]
    uint32_t a00 = (uint32_t)e_top, a01 = (uint32_t)(e_top >> 32);
    uint32_t a10 = (uint32_t)e_bot, a11 = (uint32_t)(e_bot >> 32);

    float f[40];
#pragma unroll
    for (int c = 0; c < 8; c++) {
        f[c]      = dec(a00, c);
        f[8 + c]  = dec(a01, c);
        f[16 + c] = dec(a10, c);
        f[24 + c] = dec(a11, c);
    }

    // g1 taps: when qx0 == -1, the x1 tap is texel 0 = LOW half of entry at cx=0.
    uint32_t et_lo = (uint32_t)et, et_hi = (uint32_t)(et >> 32);
    uint32_t eb_lo = (uint32_t)eb, eb_hi = (uint32_t)(eb >> 32);
    uint32_t p00 = et_lo;
    uint32_t p10 = (qx0 < 0) ? et_lo : et_hi;
    uint32_t p01 = eb_lo;
    uint32_t p11 = (qx0 < 0) ? eb_lo : eb_hi;

    float w00 = __fmul_rn(wx0m, wy0m);
    float w10 = __fmul_rn(wx1m, wy0m);
    float w01 = __fmul_rn(wx0m, wy1m);
    float w11 = __fmul_rn(wx1m, wy1m);

#pragma unroll
    for (int c = 0; c < 8; c++) {
        // reference order: ((t00 + t10) + t01) + t11
        float s = __fadd_rn(
            __fadd_rn(__fadd_rn(__fmul_rn(dec(p00, c), w00),
                                __fmul_rn(dec(p10, c), w10)),
                      __fmul_rn(dec(p01, c), w01)),
            __fmul_rn(dec(p11, c), w11));
        f[32 + c] = s;
    }

    // ---------------- coalesced writeout via smem staging --------------------
    float* s = &sbuf[warp * (32 * 44) + lane * 44];
#pragma unroll
    for (int k = 0; k < 10; k++) {
        *(float4*)(s + 4 * k) =
            make_float4(f[4 * k], f[4 * k + 1], f[4 * k + 2], f[4 * k + 3]);
    }
    __syncwarp();

    const float* ws = &sbuf[warp * (32 * 44)];
    float4* go = reinterpret_cast<float4*>(out) +
                 (size_t)(blockIdx.x * 256 + warp * 32) * 10;
#pragma unroll
    for (int k = 0; k < 10; k++) {
        int wo = lane + 32 * k;        // float4 index within 320
        int pp = wo / 10;              // point within warp tile
        int jj = wo - pp * 10;         // float4 within point
        float4 v = *(const float4*)(ws + pp * 44 + jj * 4);
        __stcs(&go[wo], v);            // evict-first: don't thrash table L2 residency
    }
}

extern "C" void kernel_launch(void* const* d_in, const int* in_sizes, int n_in,
                              void* d_out, int out_size) {
    const float2* uv = (const float2*)d_in[0];
    const float*  g0 = (const float*)d_in[1];
    const float*  g1 = (const float*)d_in[2];

    void* t0 = nullptr;
    void* t1 = nullptr;
    cudaGetSymbolAddress(&t0, g_tab0);
    cudaGetSymbolAddress(&t1, g_tab1);

    pack_kernel<RES0><<<(RES0 * RES0) / 256, 256>>>(g0, (uint64_t*)t0);
    pack_kernel<RES1><<<(RES1 * RES1) / 256, 256>>>(g1, (uint64_t*)t1);
    sample_kernel<<<NPTS / 256, 256>>>(uv, (float*)d_out);
}

// round 2
// speedup vs baseline: 1.0322x; 1.0322x over previous
#include <cuda_runtime.h>
#include <cstdint>

#define RES0 2048
#define RES1 1024
#define NPTS 2097152

// Stage 1: per-texel packed 4-bit codes (8 channels -> one u32).
__device__ uint32_t g_code0[(size_t)RES0 * RES0];   // 16 MB
__device__ uint32_t g_code1[(size_t)RES1 * RES1];   //  4 MB
// Stage 2: quad tables. Entry (y,x) = codes of {(y,x),(y,x+1),(y+1,x),(y+1,x+1)},
// neighbors clamped to edge. One LDG.128 fetches all 4 corners of a sample.
__device__ uint4 g_quad0[(size_t)RES0 * RES0];      // 64 MB
__device__ uint4 g_quad1[(size_t)RES1 * RES1];      // 16 MB

// codes = clip(round((v + 15/32) * 16), 0, 15); __float2int_rn = round-half-even
// matching jnp.round; op order matches reference exactly.
__device__ __forceinline__ uint32_t quant_code(float v) {
    float t = __fmul_rn(__fadd_rn(v, 0.46875f), 16.0f);
    int c = __float2int_rn(t);
    c = max(0, min(15, c));
    return (uint32_t)c;
}

// Exact dequant of nibble i: c/16 - 15/32 via bit trick (all steps exact).
__device__ __forceinline__ float dec(uint32_t p, int i) {
    uint32_t u = 0x3F800000u | (((p >> (4 * i)) & 0xFu) << 19);
    return __uint_as_float(u) - 1.46875f;
}

// ---------------- pass 1: quantize 4 texels per thread (vectorized) ---------
__global__ __launch_bounds__(256) void code_kernel(const float* __restrict__ g,
                                                   uint32_t* __restrict__ code,
                                                   int total) {
    int i4 = (blockIdx.x * 256 + threadIdx.x) * 4;
    if (i4 >= total) return;
    uint32_t c0 = 0, c1 = 0, c2 = 0, c3 = 0;
#pragma unroll
    for (int ch = 0; ch < 8; ch++) {
        float4 v = *(const float4*)(g + (size_t)ch * total + i4);
        c0 |= quant_code(v.x) << (4 * ch);
        c1 |= quant_code(v.y) << (4 * ch);
        c2 |= quant_code(v.z) << (4 * ch);
        c3 |= quant_code(v.w) << (4 * ch);
    }
    *(uint4*)(code + i4) = make_uint4(c0, c1, c2, c3);
}

// ---------------- pass 2: assemble quad entries (streaming, coalesced) ------
template <int RES>
__global__ __launch_bounds__(256) void quad_kernel(const uint32_t* __restrict__ code,
                                                   uint4* __restrict__ quad) {
    int idx = blockIdx.x * 256 + threadIdx.x;
    int x = idx & (RES - 1);
    int y = idx / RES;
    int dx = (x < RES - 1) ? 1 : 0;
    int dy = (y < RES - 1) ? RES : 0;
    uint32_t a = __ldg(code + idx);
    uint32_t b = __ldg(code + idx + dx);
    uint32_t c = __ldg(code + idx + dy);
    uint32_t d = __ldg(code + idx + dy + dx);
    quad[idx] = make_uint4(a, b, c, d);
}

// ---------------- sample: 2 gathers per point ------------------------------
__global__ __launch_bounds__(256) void sample_kernel(const float2* __restrict__ uv,
                                                     float* __restrict__ out) {
    // Per-warp staging: 32 points x 44-word stride (40 data + 4 pad),
    // conflict-free STS.128 / LDS.128, then fully coalesced STG.128.
    __shared__ __align__(16) float sbuf[8 * 32 * 44];

    int tid = threadIdx.x;
    int lane = tid & 31;
    int warp = tid >> 5;
    int i = blockIdx.x * 256 + tid;

    float2 p = uv[i];

    // feat0 indices: pos = uv*2048 - 0.5 ; x0 = clip(floor(pos), 0, 2046)
    float px = fmaf(p.x, 2048.0f, -0.5f);
    float py = fmaf(p.y, 2048.0f, -0.5f);
    int x0 = min(max((int)floorf(px), 0), RES0 - 2);
    int y0 = min(max((int)floorf(py), 0), RES0 - 2);

    // feat1 indices: ix = u*1024 - 0.5 (algebraically == grid_sample formula, exact)
    float ix = fmaf(p.x, 1024.0f, -0.5f);
    float iy = fmaf(p.y, 1024.0f, -0.5f);
    float fx0 = floorf(ix), fy0 = floorf(iy);
    int qx0 = (int)fx0;  // in [-1, 1023]
    int qy0 = (int)fy0;
    int cx = max(qx0, 0);
    int cy = max(qy0, 0);

    // Issue both gathers up front (independent 16B loads, L2-resident tables).
    uint4 q0 = __ldg(&g_quad0[(size_t)y0 * RES0 + x0]);   // a00,a01,a10,a11
    uint4 q1 = __ldg(&g_quad1[(size_t)cy * RES1 + cx]);

    // feat1 weights with zeros-padding via weight masking.
    float wx1 = __fsub_rn(ix, fx0), wx0 = __fsub_rn(1.0f, wx1);
    float wy1 = __fsub_rn(iy, fy0), wy0 = __fsub_rn(1.0f, wy1);
    float wx0m = (qx0 >= 0) ? wx0 : 0.0f;
    float wx1m = (qx0 + 1 <= RES1 - 1) ? wx1 : 0.0f;
    float wy0m = (qy0 >= 0) ? wy0 : 0.0f;
    float wy1m = (qy0 + 1 <= RES1 - 1) ? wy1 : 0.0f;
    float w00 = __fmul_rn(wx0m, wy0m);
    float w10 = __fmul_rn(wx1m, wy0m);
    float w01 = __fmul_rn(wx0m, wy1m);
    float w11 = __fmul_rn(wx1m, wy1m);

    // Tap slot-selection for clamped/OOB cases:
    //  qx0 < 0 -> x1 tap is texel 0 (slot column 0); x0 tap weight is 0.
    //  qy0 < 0 -> y1 taps are texel row 0 (slots 0/1); y0 tap weights are 0.
    uint32_t p00 = q1.x;
    uint32_t p10 = (qx0 < 0) ? q1.x : q1.y;
    uint32_t p01 = (qy0 < 0) ? q1.x : q1.z;
    uint32_t p11 = (qy0 < 0) ? ((qx0 < 0) ? q1.x : q1.y)
                             : ((qx0 < 0) ? q1.z : q1.w);

    float f[40];
#pragma unroll
    for (int c = 0; c < 8; c++) {
        f[c]      = dec(q0.x, c);
        f[8 + c]  = dec(q0.y, c);
        f[16 + c] = dec(q0.z, c);
        f[24 + c] = dec(q0.w, c);
    }
#pragma unroll
    for (int c = 0; c < 8; c++) {
        // reference order: ((t00 + t10) + t01) + t11
        float s = __fadd_rn(
            __fadd_rn(__fadd_rn(__fmul_rn(dec(p00, c), w00),
                                __fmul_rn(dec(p10, c), w10)),
                      __fmul_rn(dec(p01, c), w01)),
            __fmul_rn(dec(p11, c), w11));
        f[32 + c] = s;
    }

    // Coalesced writeout via smem staging.
    float* s = &sbuf[warp * (32 * 44) + lane * 44];
#pragma unroll
    for (int k = 0; k < 10; k++) {
        *(float4*)(s + 4 * k) =
            make_float4(f[4 * k], f[4 * k + 1], f[4 * k + 2], f[4 * k + 3]);
    }
    __syncwarp();

    const float* ws = &sbuf[warp * (32 * 44)];
    float4* go = reinterpret_cast<float4*>(out) +
                 (size_t)(blockIdx.x * 256 + warp * 32) * 10;
#pragma unroll
    for (int k = 0; k < 10; k++) {
        int wo = lane + 32 * k;        // float4 index within the warp's 320
        int pp = wo / 10;              // point within warp tile
        int jj = wo - pp * 10;         // float4 within point
        float4 v = *(const float4*)(ws + pp * 44 + jj * 4);
        __stcs(&go[wo], v);            // evict-first: protect table L2 residency
    }
}

extern "C" void kernel_launch(void* const* d_in, const int* in_sizes, int n_in,
                              void* d_out, int out_size) {
    const float2* uv = (const float2*)d_in[0];
    const float*  g0 = (const float*)d_in[1];
    const float*  g1 = (const float*)d_in[2];

    void *c0p, *c1p, *q0p, *q1p;
    cudaGetSymbolAddress(&c0p, g_code0);
    cudaGetSymbolAddress(&c1p, g_code1);
    cudaGetSymbolAddress(&q0p, g_quad0);
    cudaGetSymbolAddress(&q1p, g_quad1);

    code_kernel<<<(RES0 * RES0 / 4 + 255) / 256, 256>>>(g0, (uint32_t*)c0p, RES0 * RES0);
    code_kernel<<<(RES1 * RES1 / 4 + 255) / 256, 256>>>(g1, (uint32_t*)c1p, RES1 * RES1);
    quad_kernel<RES0><<<(RES0 * RES0) / 256, 256>>>((const uint32_t*)c0p, (uint4*)q0p);
    quad_kernel<RES1><<<(RES1 * RES1) / 256, 256>>>((const uint32_t*)c1p, (uint4*)q1p);
    sample_kernel<<<NPTS / 256, 256>>>(uv, (float*)d_out);
}

// round 4
// speedup vs baseline: 1.0702x; 1.0368x over previous
#include <cuda_runtime.h>
#include <cstdint>

#define RES0 2048
#define RES1 1024
#define NPTS 2097152

// Quad tables. Entry (y,x) = packed 4-bit codes (8ch/u32) of the 4 corners
// {(y,x),(y,x+1),(y+1,x),(y+1,x+1)}, neighbors clamped to edge.
// One LDG.128 fetches all corners of a sample. 64 MB + 16 MB -> L2-pinnable.
__device__ uint4 g_quad0[(size_t)RES0 * RES0];
__device__ uint4 g_quad1[(size_t)RES1 * RES1];

// codes = clip(round((v + 15/32) * 16), 0, 15); round-half-even matches jnp.round.
__device__ __forceinline__ uint32_t quant_code(float v) {
    float t = __fmul_rn(__fadd_rn(v, 0.46875f), 16.0f);
    int c = __float2int_rn(t);
    return (uint32_t)max(0, min(15, c));
}

// Exact dequant of nibble i: c/16 - 15/32. SHF + LOP3 + FADD (3 instr).
__device__ __forceinline__ float dec(uint32_t p, int i) {
    uint32_t t = (i < 5) ? (p << (19 - 4 * i)) : (p >> (4 * i - 19));
    uint32_t u = (t & 0x00780000u) | 0x3F800000u;
    return __uint_as_float(u) - 1.46875f;
}

// L2 evict_last via createpolicy + cache_hint (the form ptxas accepts for v4.u32).
__device__ __forceinline__ void st_evict_last(uint4* dst, uint4 q) {
    asm volatile(
        "{\n\t"
        ".reg .b64 pol;\n\t"
        "createpolicy.fractional.L2::evict_last.b64 pol, 1.0;\n\t"
        "st.global.L2::cache_hint.v4.u32 [%0], {%1,%2,%3,%4}, pol;\n\t"
        "}"
        :: "l"(dst), "r"(q.x), "r"(q.y), "r"(q.z), "r"(q.w) : "memory");
}

__device__ __forceinline__ uint4 ld_evict_last(const uint4* p) {
    uint4 q;
    asm volatile(
        "{\n\t"
        ".reg .b64 pol;\n\t"
        "createpolicy.fractional.L2::evict_last.b64 pol, 1.0;\n\t"
        "ld.global.L2::cache_hint.v4.u32 {%0,%1,%2,%3}, [%4], pol;\n\t"
        "}"
        : "=r"(q.x), "=r"(q.y), "=r"(q.z), "=r"(q.w) : "l"(p));
    return q;
}

// ---------------- fused pack: quantize tile+halo in smem, emit quads --------
template <int RES>
__global__ __launch_bounds__(512) void pack_kernel(const float* __restrict__ g,
                                                   uint4* __restrict__ quad) {
    __shared__ uint32_t sc[17][33];
    int bx = blockIdx.x * 32;
    int by = blockIdx.y * 16;
    int tid = threadIdx.x;

    // Phase A: quantize the 33x17 tile+halo (561 texels), 8 channels -> u32.
    for (int p = tid; p < 17 * 33; p += 512) {
        int ly = p / 33, lx = p - ly * 33;
        int gx = min(bx + lx, RES - 1);
        int gy = min(by + ly, RES - 1);
        size_t base = (size_t)gy * RES + gx;
        uint32_t pk = 0;
#pragma unroll
        for (int c = 0; c < 8; c++) {
            float v = __ldg(g + (size_t)c * RES * RES + base);
            pk |= quant_code(v) << (4 * c);
        }
        sc[ly][lx] = pk;
    }
    __syncthreads();

    // Phase B: one quad entry per thread, pinned into L2.
    int lx = tid & 31, ly = tid >> 5;
    uint4 q = make_uint4(sc[ly][lx], sc[ly][lx + 1],
                         sc[ly + 1][lx], sc[ly + 1][lx + 1]);
    st_evict_last(&quad[(size_t)(by + ly) * RES + bx + lx], q);
}

// ---------------- sample: 2 L2-resident gathers per point -------------------
__global__ __launch_bounds__(256) void sample_kernel(const float2* __restrict__ uv,
                                                     float* __restrict__ out) {
    // Per-warp staging: 32 points x 44-word stride -> conflict-free
    // STS.128 / LDS.128, then fully coalesced STG.128.
    __shared__ __align__(16) float sbuf[8 * 32 * 44];

    int tid = threadIdx.x;
    int lane = tid & 31;
    int warp = tid >> 5;
    int i = blockIdx.x * 256 + tid;

    float2 p = __ldcs(&uv[i]);   // read-once stream

    // feat0 indices: pos = uv*2048 - 0.5 ; x0 = clip(floor(pos), 0, 2046)
    float px = fmaf(p.x, 2048.0f, -0.5f);
    float py = fmaf(p.y, 2048.0f, -0.5f);
    int x0 = min(max((int)floorf(px), 0), RES0 - 2);
    int y0 = min(max((int)floorf(py), 0), RES0 - 2);

    // feat1 indices: ix = u*1024 - 0.5 (== grid_sample formula, exact)
    float ix = fmaf(p.x, 1024.0f, -0.5f);
    float iy = fmaf(p.y, 1024.0f, -0.5f);
    float fx0 = floorf(ix), fy0 = floorf(iy);
    int qx0 = (int)fx0;  // in [-1, 1023]
    int qy0 = (int)fy0;
    int cx = max(qx0, 0);
    int cy = max(qy0, 0);

    // Both gathers issued up front; evict_last keeps tables L2-resident.
    uint4 q0 = ld_evict_last(&g_quad0[(size_t)y0 * RES0 + x0]);
    uint4 q1 = ld_evict_last(&g_quad1[(size_t)cy * RES1 + cx]);

    // feat1 weights, zeros-padding via weight masking.
    float wx1 = __fsub_rn(ix, fx0), wx0 = __fsub_rn(1.0f, wx1);
    float wy1 = __fsub_rn(iy, fy0), wy0 = __fsub_rn(1.0f, wy1);
    float wx0m = (qx0 >= 0) ? wx0 : 0.0f;
    float wx1m = (qx0 + 1 <= RES1 - 1) ? wx1 : 0.0f;
    float wy0m = (qy0 >= 0) ? wy0 : 0.0f;
    float wy1m = (qy0 + 1 <= RES1 - 1) ? wy1 : 0.0f;
    float w00 = __fmul_rn(wx0m, wy0m);
    float w10 = __fmul_rn(wx1m, wy0m);
    float w01 = __fmul_rn(wx0m, wy1m);
    float w11 = __fmul_rn(wx1m, wy1m);

    // Slot-select for clamped/OOB taps (matching zero-weight masking).
    uint32_t p00 = q1.x;
    uint32_t p10 = (qx0 < 0) ? q1.x : q1.y;
    uint32_t p01 = (qy0 < 0) ? q1.x : q1.z;
    uint32_t p11 = (qy0 < 0) ? ((qx0 < 0) ? q1.x : q1.y)
                             : ((qx0 < 0) ? q1.z : q1.w);

    float f[40];
#pragma unroll
    for (int c = 0; c < 8; c++) {
        f[c]      = dec(q0.x, c);
        f[8 + c]  = dec(q0.y, c);
        f[16 + c] = dec(q0.z, c);
        f[24 + c] = dec(q0.w, c);
    }
#pragma unroll
    for (int c = 0; c < 8; c++) {
        // reference order: ((t00 + t10) + t01) + t11
        float s = __fadd_rn(
            __fadd_rn(__fadd_rn(__fmul_rn(dec(p00, c), w00),
                                __fmul_rn(dec(p10, c), w10)),
                      __fmul_rn(dec(p01, c), w01)),
            __fmul_rn(dec(p11, c), w11));
        f[32 + c] = s;
    }

    // Coalesced writeout via smem staging.
    float* s = &sbuf[warp * (32 * 44) + lane * 44];
#pragma unroll
    for (int k = 0; k < 10; k++) {
        *(float4*)(s + 4 * k) =
            make_float4(f[4 * k], f[4 * k + 1], f[4 * k + 2], f[4 * k + 3]);
    }
    __syncwarp();

    const float* ws = &sbuf[warp * (32 * 44)];
    float4* go = reinterpret_cast<float4*>(out) +
                 (size_t)(blockIdx.x * 256 + warp * 32) * 10;
#pragma unroll
    for (int k = 0; k < 10; k++) {
        int wo = lane + 32 * k;        // float4 index within the warp's 320
        int pp = wo / 10;              // point within warp tile
        int jj = wo - pp * 10;         // float4 within point
        float4 v = *(const float4*)(ws + pp * 44 + jj * 4);
        __stcs(&go[wo], v);            // evict-first: protect table residency
    }
}

extern "C" void kernel_launch(void* const* d_in, const int* in_sizes, int n_in,
                              void* d_out, int out_size) {
    const float2* uv = (const float2*)d_in[0];
    const float*  g0 = (const float*)d_in[1];
    const float*  g1 = (const float*)d_in[2];

    void *q0p, *q1p;
    cudaGetSymbolAddress(&q0p, g_quad0);
    cudaGetSymbolAddress(&q1p, g_quad1);

    dim3 grid0(RES0 / 32, RES0 / 16);
    dim3 grid1(RES1 / 32, RES1 / 16);
    pack_kernel<RES0><<<grid0, 512>>>(g0, (uint4*)q0p);
    pack_kernel<RES1><<<grid1, 512>>>(g1, (uint4*)q1p);
    sample_kernel<<<NPTS / 256, 256>>>(uv, (float*)d_out);
}

// round 5
// speedup vs baseline: 1.3912x; 1.3000x over previous
#include <cuda_runtime.h>
#include <cstdint>

#define RES0 2048
#define RES1 1024
#define NPTS 2097152

// Quad tables. Entry (y,x) = packed 4-bit codes (8ch/u32) of the 4 corners
// {(y,x),(y,x+1),(y+1,x),(y+1,x+1)}, neighbors clamped to edge.
__device__ uint4 g_quad0[(size_t)RES0 * RES0];
__device__ uint4 g_quad1[(size_t)RES1 * RES1];

// codes = clip(round((v + 15/32) * 16), 0, 15); round-half-even matches jnp.round.
__device__ __forceinline__ uint32_t quant_code(float v) {
    float t = __fmul_rn(__fadd_rn(v, 0.46875f), 16.0f);
    int c = __float2int_rn(t);
    return (uint32_t)max(0, min(15, c));
}

// Exact dequant of nibble i: c/16 - 15/32. SHF + LOP3 + FADD.
__device__ __forceinline__ float dec(uint32_t p, int i) {
    uint32_t t = (i < 5) ? (p << (19 - 4 * i)) : (p >> (4 * i - 19));
    uint32_t u = (t & 0x00780000u) | 0x3F800000u;
    return __uint_as_float(u) - 1.46875f;
}

// L2 evict_last via createpolicy + cache_hint.
__device__ __forceinline__ void st_evict_last(uint4* dst, uint4 q) {
    asm volatile(
        "{\n\t.reg .b64 pol;\n\t"
        "createpolicy.fractional.L2::evict_last.b64 pol, 1.0;\n\t"
        "st.global.L2::cache_hint.v4.u32 [%0], {%1,%2,%3,%4}, pol;\n\t}"
        :: "l"(dst), "r"(q.x), "r"(q.y), "r"(q.z), "r"(q.w) : "memory");
}

__device__ __forceinline__ uint4 ld_evict_last(const uint4* p) {
    uint4 q;
    asm volatile(
        "{\n\t.reg .b64 pol;\n\t"
        "createpolicy.fractional.L2::evict_last.b64 pol, 1.0;\n\t"
        "ld.global.L2::cache_hint.v4.u32 {%0,%1,%2,%3}, [%4], pol;\n\t}"
        : "=r"(q.x), "=r"(q.y), "=r"(q.z), "=r"(q.w) : "l"(p));
    return q;
}

// ---------------- fused pack: both grids in ONE launch ----------------------
template <int RES>
__device__ __forceinline__ void pack_body(const float* __restrict__ g,
                                          uint4* __restrict__ quad, int blk) {
    __shared__ uint32_t sc[17][33];
    int bx = (blk % (RES / 32)) * 32;
    int by = (blk / (RES / 32)) * 16;
    int tid = threadIdx.x;

    // Phase A: quantize the 33x17 tile+halo, 8 channels -> u32 each.
    for (int p = tid; p < 17 * 33; p += 512) {
        int ly = p / 33, lx = p - ly * 33;
        int gx = min(bx + lx, RES - 1);
        int gy = min(by + ly, RES - 1);
        size_t base = (size_t)gy * RES + gx;
        uint32_t pk = 0;
#pragma unroll
        for (int c = 0; c < 8; c++) {
            float v = __ldg(g + (size_t)c * RES * RES + base);
            pk |= quant_code(v) << (4 * c);
        }
        sc[ly][lx] = pk;
    }
    __syncthreads();

    // Phase B: one quad entry per thread, pinned into L2.
    int lx = tid & 31, ly = tid >> 5;
    uint4 q = make_uint4(sc[ly][lx], sc[ly][lx + 1],
                         sc[ly + 1][lx], sc[ly + 1][lx + 1]);
    st_evict_last(&quad[(size_t)(by + ly) * RES + bx + lx], q);
}

#define NBLK0 ((RES0 / 32) * (RES0 / 16))   // 8192
#define NBLK1 ((RES1 / 32) * (RES1 / 16))   // 2048

__global__ __launch_bounds__(512) void pack_all(const float* __restrict__ g0,
                                                const float* __restrict__ g1) {
    int b = blockIdx.x;
    if (b < NBLK0) pack_body<RES0>(g0, g_quad0, b);
    else           pack_body<RES1>(g1, g_quad1, b - NBLK0);
}

// ---------------- sample: 2 gathers/point, slim smem staging ----------------
// Staging per point: 12 words = [q0 codes x4 | feat1 floats x8]. 12 KB/block
// -> occupancy becomes thread-limited (64 warps/SM vs 40 before).
__global__ __launch_bounds__(256) void sample_kernel(const float2* __restrict__ uv,
                                                     float* __restrict__ out) {
    __shared__ __align__(16) float sbuf[8 * 32 * 12];

    int tid = threadIdx.x;
    int lane = tid & 31;
    int warp = tid >> 5;
    int i = blockIdx.x * 256 + tid;

    float2 p = __ldcs(&uv[i]);

    // feat0 indices: pos = uv*2048 - 0.5 ; x0 = clip(floor(pos), 0, 2046)
    float px = fmaf(p.x, 2048.0f, -0.5f);
    float py = fmaf(p.y, 2048.0f, -0.5f);
    int x0 = min(max((int)floorf(px), 0), RES0 - 2);
    int y0 = min(max((int)floorf(py), 0), RES0 - 2);

    // feat1 indices: ix = u*1024 - 0.5 (== grid_sample formula, exact)
    float ix = fmaf(p.x, 1024.0f, -0.5f);
    float iy = fmaf(p.y, 1024.0f, -0.5f);
    float fx0 = floorf(ix), fy0 = floorf(iy);
    int qx0 = (int)fx0;
    int qy0 = (int)fy0;
    int cx = max(qx0, 0);
    int cy = max(qy0, 0);

    uint4 q0 = ld_evict_last(&g_quad0[(size_t)y0 * RES0 + x0]);
    uint4 q1 = ld_evict_last(&g_quad1[(size_t)cy * RES1 + cx]);

    // feat1 weights (zeros-padding via weight masking).
    float wx1 = __fsub_rn(ix, fx0), wx0 = __fsub_rn(1.0f, wx1);
    float wy1 = __fsub_rn(iy, fy0), wy0 = __fsub_rn(1.0f, wy1);
    float wx0m = (qx0 >= 0) ? wx0 : 0.0f;
    float wx1m = (qx0 + 1 <= RES1 - 1) ? wx1 : 0.0f;
    float wy0m = (qy0 >= 0) ? wy0 : 0.0f;
    float wy1m = (qy0 + 1 <= RES1 - 1) ? wy1 : 0.0f;
    float w00 = __fmul_rn(wx0m, wy0m);
    float w10 = __fmul_rn(wx1m, wy0m);
    float w01 = __fmul_rn(wx0m, wy1m);
    float w11 = __fmul_rn(wx1m, wy1m);

    // Slot-select for clamped/OOB taps.
    uint32_t p00 = q1.x;
    uint32_t p10 = (qx0 < 0) ? q1.x : q1.y;
    uint32_t p01 = (qy0 < 0) ? q1.x : q1.z;
    uint32_t p11 = (qy0 < 0) ? ((qx0 < 0) ? q1.x : q1.y)
                             : ((qx0 < 0) ? q1.z : q1.w);

    // feat1: 8 channels, reference op order ((t00+t10)+t01)+t11.
    float ff[8];
#pragma unroll
    for (int c = 0; c < 8; c++) {
        ff[c] = __fadd_rn(
            __fadd_rn(__fadd_rn(__fmul_rn(dec(p00, c), w00),
                                __fmul_rn(dec(p10, c), w10)),
                      __fmul_rn(dec(p01, c), w01)),
            __fmul_rn(dec(p11, c), w11));
    }

    // Stage: 3x STS.128 per point (raw codes + decoded feat1).
    float* s = &sbuf[warp * (32 * 12) + lane * 12];
    *(uint4*)s = q0;
    *(float4*)(s + 4) = make_float4(ff[0], ff[1], ff[2], ff[3]);
    *(float4*)(s + 8) = make_float4(ff[4], ff[5], ff[6], ff[7]);
    __syncwarp();

    // Coalesced readout: decode feat0 nibbles on the fly.
    const float* ws = &sbuf[warp * (32 * 12)];
    float4* go = reinterpret_cast<float4*>(out) +
                 (size_t)(blockIdx.x * 256 + warp * 32) * 10;
#pragma unroll
    for (int k = 0; k < 10; k++) {
        int wo = lane + 32 * k;        // float4 index within the warp's 320
        int pp = wo / 10;              // point within warp tile
        int jj = wo - pp * 10;         // float4 within point
        const float* sp = ws + pp * 12;
        float4 v;
        if (jj < 8) {
            uint32_t code = __float_as_uint(sp[jj >> 1]);  // corner jj>>1
            int cb = (jj & 1) * 4;
            v = make_float4(dec(code, cb), dec(code, cb + 1),
                            dec(code, cb + 2), dec(code, cb + 3));
        } else {
            v = *(const float4*)(sp + 4 + (jj - 8) * 4);   // staged feat1
        }
        __stcs(&go[wo], v);
    }
}

extern "C" void kernel_launch(void* const* d_in, const int* in_sizes, int n_in,
                              void* d_out, int out_size) {
    const float2* uv = (const float2*)d_in[0];
    const float*  g0 = (const float*)d_in[1];
    const float*  g1 = (const float*)d_in[2];

    pack_all<<<NBLK0 + NBLK1, 512>>>(g0, g1);
    sample_kernel<<<NPTS / 256, 256>>>(uv, (float*)d_out);
}

// round 6
// speedup vs baseline: 1.6328x; 1.1736x over previous
#include <cuda_runtime.h>
#include <cstdint>

#define RES0 2048
#define RES1 1024
#define NPTS 2097152

// Quad tables. Entry (y,x) = packed 4-bit codes (8ch/u32) of the 4 corners
// {(y,x),(y,x+1),(y+1,x),(y+1,x+1)}, neighbors clamped to edge.
__device__ uint4 g_quad0[(size_t)RES0 * RES0];
__device__ uint4 g_quad1[(size_t)RES1 * RES1];

// codes = clip(round((v + 15/32) * 16), 0, 15); round-half-even matches jnp.round.
__device__ __forceinline__ uint32_t quant_code(float v) {
    float t = __fmul_rn(__fadd_rn(v, 0.46875f), 16.0f);
    int c = __float2int_rn(t);
    return (uint32_t)max(0, min(15, c));
}

// Exact dequant of nibble i: c/16 - 15/32. SHF + LOP3 + FADD.
__device__ __forceinline__ float dec(uint32_t p, int i) {
    uint32_t t = (i < 5) ? (p << (19 - 4 * i)) : (p >> (4 * i - 19));
    uint32_t u = (t & 0x00780000u) | 0x3F800000u;
    return __uint_as_float(u) - 1.46875f;
}

// L2 evict_last via createpolicy + cache_hint.
__device__ __forceinline__ void st_evict_last(uint4* dst, uint4 q) {
    asm volatile(
        "{\n\t.reg .b64 pol;\n\t"
        "createpolicy.fractional.L2::evict_last.b64 pol, 1.0;\n\t"
        "st.global.L2::cache_hint.v4.u32 [%0], {%1,%2,%3,%4}, pol;\n\t}"
        :: "l"(dst), "r"(q.x), "r"(q.y), "r"(q.z), "r"(q.w) : "memory");
}

__device__ __forceinline__ uint4 ld_evict_last(const uint4* p) {
    uint4 q;
    asm volatile(
        "{\n\t.reg .b64 pol;\n\t"
        "createpolicy.fractional.L2::evict_last.b64 pol, 1.0;\n\t"
        "ld.global.L2::cache_hint.v4.u32 {%0,%1,%2,%3}, [%4], pol;\n\t}"
        : "=r"(q.x), "=r"(q.y), "=r"(q.z), "=r"(q.w) : "l"(p));
    return q;
}

// ---------------- fused pack: both grids in ONE launch ----------------------
// Input reads are STREAMING (evict_first) so the evict_last table lines are
// the only L2-persistent data -> sample's gathers can hit in L2.
template <int RES>
__device__ __forceinline__ void pack_body(const float* __restrict__ g,
                                          uint4* __restrict__ quad, int blk) {
    __shared__ uint32_t sc[17][33];
    int bx = (blk % (RES / 32)) * 32;
    int by = (blk / (RES / 32)) * 16;
    int tid = threadIdx.x;

    for (int p = tid; p < 17 * 33; p += 512) {
        int ly = p / 33, lx = p - ly * 33;
        int gx = min(bx + lx, RES - 1);
        int gy = min(by + ly, RES - 1);
        size_t base = (size_t)gy * RES + gx;
        uint32_t pk = 0;
#pragma unroll
        for (int c = 0; c < 8; c++) {
            float v = __ldcs(g + (size_t)c * RES * RES + base);  // evict_first
            pk |= quant_code(v) << (4 * c);
        }
        sc[ly][lx] = pk;
    }
    __syncthreads();

    int lx = tid & 31, ly = tid >> 5;
    uint4 q = make_uint4(sc[ly][lx], sc[ly][lx + 1],
                         sc[ly + 1][lx], sc[ly + 1][lx + 1]);
    st_evict_last(&quad[(size_t)(by + ly) * RES + bx + lx], q);
}

#define NBLK0 ((RES0 / 32) * (RES0 / 16))   // 8192
#define NBLK1 ((RES1 / 32) * (RES1 / 16))   // 2048

__global__ __launch_bounds__(512) void pack_all(const float* __restrict__ g0,
                                                const float* __restrict__ g1) {
    int b = blockIdx.x;
    if (b < NBLK0) pack_body<RES0>(g0, g_quad0, b);
    else           pack_body<RES1>(g1, g_quad1, b - NBLK0);
}

// ---------------- sample: 2 gathers/point, slim smem staging ----------------
__global__ __launch_bounds__(256) void sample_kernel(const float2* __restrict__ uv,
                                                     float* __restrict__ out) {
    __shared__ __align__(16) float sbuf[8 * 32 * 12];

    int tid = threadIdx.x;
    int lane = tid & 31;
    int warp = tid >> 5;
    int i = blockIdx.x * 256 + tid;

    float2 p = __ldcs(&uv[i]);

    // feat0 indices: pos = uv*2048 - 0.5 ; x0 = clip(floor(pos), 0, 2046)
    float px = fmaf(p.x, 2048.0f, -0.5f);
    float py = fmaf(p.y, 2048.0f, -0.5f);
    int x0 = min(max((int)floorf(px), 0), RES0 - 2);
    int y0 = min(max((int)floorf(py), 0), RES0 - 2);

    // feat1 indices: ix = u*1024 - 0.5 (== grid_sample formula, exact)
    float ix = fmaf(p.x, 1024.0f, -0.5f);
    float iy = fmaf(p.y, 1024.0f, -0.5f);
    float fx0 = floorf(ix), fy0 = floorf(iy);
    int qx0 = (int)fx0;
    int qy0 = (int)fy0;
    int cx = max(qx0, 0);
    int cy = max(qy0, 0);

    uint4 q0 = ld_evict_last(&g_quad0[(size_t)y0 * RES0 + x0]);
    uint4 q1 = ld_evict_last(&g_quad1[(size_t)cy * RES1 + cx]);

    // feat1 weights (zeros-padding via weight masking).
    float wx1 = __fsub_rn(ix, fx0), wx0 = __fsub_rn(1.0f, wx1);
    float wy1 = __fsub_rn(iy, fy0), wy0 = __fsub_rn(1.0f, wy1);
    float wx0m = (qx0 >= 0) ? wx0 : 0.0f;
    float wx1m = (qx0 + 1 <= RES1 - 1) ? wx1 : 0.0f;
    float wy0m = (qy0 >= 0) ? wy0 : 0.0f;
    float wy1m = (qy0 + 1 <= RES1 - 1) ? wy1 : 0.0f;
    float w00 = wx0m * wy0m;
    float w10 = wx1m * wy0m;
    float w01 = wx0m * wy1m;
    float w11 = wx1m * wy1m;

    // Slot-select for clamped/OOB taps.
    uint32_t p00 = q1.x;
    uint32_t p10 = (qx0 < 0) ? q1.x : q1.y;
    uint32_t p01 = (qy0 < 0) ? q1.x : q1.z;
    uint32_t p11 = (qy0 < 0) ? ((qx0 < 0) ? q1.x : q1.y)
                             : ((qx0 < 0) ? q1.z : q1.w);

    // feat1: FMA accumulation (within 1e-6 of reference order; tol is 1e-3).
    float ff[8];
#pragma unroll
    for (int c = 0; c < 8; c++) {
        float s = dec(p00, c) * w00;
        s = fmaf(dec(p10, c), w10, s);
        s = fmaf(dec(p01, c), w01, s);
        s = fmaf(dec(p11, c), w11, s);
        ff[c] = s;
    }

    // Stage: 3x STS.128 per point (raw codes + decoded feat1).
    float* s = &sbuf[warp * (32 * 12) + lane * 12];
    *(uint4*)s = q0;
    *(float4*)(s + 4) = make_float4(ff[0], ff[1], ff[2], ff[3]);
    *(float4*)(s + 8) = make_float4(ff[4], ff[5], ff[6], ff[7]);
    __syncwarp();

    // Coalesced readout: decode feat0 nibbles on the fly.
    const float* ws = &sbuf[warp * (32 * 12)];
    float4* go = reinterpret_cast<float4*>(out) +
                 (size_t)(blockIdx.x * 256 + warp * 32) * 10;
#pragma unroll
    for (int k = 0; k < 10; k++) {
        int wo = lane + 32 * k;        // float4 index within the warp's 320
        int pp = wo / 10;              // point within warp tile
        int jj = wo - pp * 10;         // float4 within point
        const float* sp = ws + pp * 12;
        float4 v;
        if (jj < 8) {
            uint32_t code = __float_as_uint(sp[jj >> 1]);  // corner jj>>1
            int cb = (jj & 1) * 4;
            v = make_float4(dec(code, cb), dec(code, cb + 1),
                            dec(code, cb + 2), dec(code, cb + 3));
        } else {
            v = *(const float4*)(sp + 4 + (jj - 8) * 4);   // staged feat1
        }
        __stcs(&go[wo], v);
    }
}

extern "C" void kernel_launch(void* const* d_in, const int* in_sizes, int n_in,
                              void* d_out, int out_size) {
    const float2* uv = (const float2*)d_in[0];
    const float*  g0 = (const float*)d_in[1];
    const float*  g1 = (const float*)d_in[2];

    pack_all<<<NBLK0 + NBLK1, 512>>>(g0, g1);
    sample_kernel<<<NPTS / 256, 256>>>(uv, (float*)d_out);
}

// round 7
// speedup vs baseline: 1.7596x; 1.0776x over previous
#include <cuda_runtime.h>
#include <cstdint>

#define RES0 2048
#define RES1 1024
#define NPTS 2097152

// g0: dup-pair table, entry (y,x) = codes(y,x) | codes(y,min(x+1,RES-1))<<32.
// 32 MB. Sample does two LDG.64 (rows y0, y0+1).
__device__ uint64_t g_pair0[(size_t)RES0 * RES0];
// g1: quad table, entry (y,x) = codes of the 4 corners (clamped). 16 MB, one LDG.128.
__device__ uint4 g_quad1[(size_t)RES1 * RES1];
// Total 48 MB -> survives in L2 by LRU since all other traffic is evict-first.

// codes = clip(round((v + 15/32) * 16), 0, 15); round-half-even matches jnp.round.
__device__ __forceinline__ uint32_t quant_code(float v) {
    float t = __fmul_rn(__fadd_rn(v, 0.46875f), 16.0f);
    int c = __float2int_rn(t);
    return (uint32_t)max(0, min(15, c));
}

// Exact dequant of nibble i: c/16 - 15/32. SHF + LOP3 + FADD.
__device__ __forceinline__ float dec(uint32_t p, int i) {
    uint32_t t = (i < 5) ? (p << (19 - 4 * i)) : (p >> (4 * i - 19));
    uint32_t u = (t & 0x00780000u) | 0x3F800000u;
    return __uint_as_float(u) - 1.46875f;
}

// ---------------- fused pack: both grids in ONE launch ----------------------
// Inputs read with __ldcs (evict_first) so table lines win L2 by default LRU.

// g0 body: x-halo only (pair entries need no y neighbor). Tile 32x16, smem 16x33.
__device__ __forceinline__ void pack_body0(const float* __restrict__ g, int blk) {
    __shared__ uint32_t sc[16][33];
    int bx = (blk % (RES0 / 32)) * 32;
    int by = (blk / (RES0 / 32)) * 16;
    int tid = threadIdx.x;

    for (int p = tid; p < 16 * 33; p += 512) {
        int ly = p / 33, lx = p - ly * 33;
        int gx = min(bx + lx, RES0 - 1);
        size_t base = (size_t)(by + ly) * RES0 + gx;
        uint32_t pk = 0;
#pragma unroll
        for (int c = 0; c < 8; c++) {
            float v = __ldcs(g + (size_t)c * RES0 * RES0 + base);
            pk |= quant_code(v) << (4 * c);
        }
        sc[ly][lx] = pk;
    }
    __syncthreads();

    int lx = tid & 31, ly = tid >> 5;
    uint64_t e = (uint64_t)sc[ly][lx] | ((uint64_t)sc[ly][lx + 1] << 32);
    g_pair0[(size_t)(by + ly) * RES0 + bx + lx] = e;
}

// g1 body: full quad (x+y halo). Tile 32x16, smem 17x33.
__device__ __forceinline__ void pack_body1(const float* __restrict__ g, int blk) {
    __shared__ uint32_t sc[17][33];
    int bx = (blk % (RES1 / 32)) * 32;
    int by = (blk / (RES1 / 32)) * 16;
    int tid = threadIdx.x;

    for (int p = tid; p < 17 * 33; p += 512) {
        int ly = p / 33, lx = p - ly * 33;
        int gx = min(bx + lx, RES1 - 1);
        int gy = min(by + ly, RES1 - 1);
        size_t base = (size_t)gy * RES1 + gx;
        uint32_t pk = 0;
#pragma unroll
        for (int c = 0; c < 8; c++) {
            float v = __ldcs(g + (size_t)c * RES1 * RES1 + base);
            pk |= quant_code(v) << (4 * c);
        }
        sc[ly][lx] = pk;
    }
    __syncthreads();

    int lx = tid & 31, ly = tid >> 5;
    g_quad1[(size_t)(by + ly) * RES1 + bx + lx] =
        make_uint4(sc[ly][lx], sc[ly][lx + 1], sc[ly + 1][lx], sc[ly + 1][lx + 1]);
}

#define NBLK0 ((RES0 / 32) * (RES0 / 16))   // 8192
#define NBLK1 ((RES1 / 32) * (RES1 / 16))   // 2048

__global__ __launch_bounds__(512) void pack_all(const float* __restrict__ g0,
                                                const float* __restrict__ g1) {
    int b = blockIdx.x;
    if (b < NBLK0) pack_body0(g0, b);
    else           pack_body1(g1, b - NBLK0);
}

// ---------------- sample: 3 gathers/point, slim smem staging ----------------
__global__ __launch_bounds__(256) void sample_kernel(const float2* __restrict__ uv,
                                                     float* __restrict__ out) {
    __shared__ __align__(16) float sbuf[8 * 32 * 12];

    int tid = threadIdx.x;
    int lane = tid & 31;
    int warp = tid >> 5;
    int i = blockIdx.x * 256 + tid;

    float2 p = __ldcs(&uv[i]);

    // feat0 indices: pos = uv*2048 - 0.5 ; x0 = clip(floor(pos), 0, 2046)
    float px = fmaf(p.x, 2048.0f, -0.5f);
    float py = fmaf(p.y, 2048.0f, -0.5f);
    int x0 = min(max((int)floorf(px), 0), RES0 - 2);
    int y0 = min(max((int)floorf(py), 0), RES0 - 2);

    // feat1 indices: ix = u*1024 - 0.5 (== grid_sample formula, exact)
    float ix = fmaf(p.x, 1024.0f, -0.5f);
    float iy = fmaf(p.y, 1024.0f, -0.5f);
    float fx0 = floorf(ix), fy0 = floorf(iy);
    int qx0 = (int)fx0;
    int qy0 = (int)fy0;
    int cx = max(qx0, 0);
    int cy = max(qy0, 0);

    // Issue all three gathers up front (independent; tables L2-resident).
    const uint64_t* r0 = g_pair0 + (size_t)y0 * RES0 + x0;
    uint64_t e_top = __ldg(r0);
    uint64_t e_bot = __ldg(r0 + RES0);
    uint4 q1 = __ldg(&g_quad1[(size_t)cy * RES1 + cx]);

    // feat1 weights (zeros-padding via weight masking).
    float wx1 = __fsub_rn(ix, fx0), wx0 = __fsub_rn(1.0f, wx1);
    float wy1 = __fsub_rn(iy, fy0), wy0 = __fsub_rn(1.0f, wy1);
    float wx0m = (qx0 >= 0) ? wx0 : 0.0f;
    float wx1m = (qx0 + 1 <= RES1 - 1) ? wx1 : 0.0f;
    float wy0m = (qy0 >= 0) ? wy0 : 0.0f;
    float wy1m = (qy0 + 1 <= RES1 - 1) ? wy1 : 0.0f;
    float w00 = wx0m * wy0m;
    float w10 = wx1m * wy0m;
    float w01 = wx0m * wy1m;
    float w11 = wx1m * wy1m;

    // Slot-select for clamped/OOB taps.
    uint32_t p00 = q1.x;
    uint32_t p10 = (qx0 < 0) ? q1.x : q1.y;
    uint32_t p01 = (qy0 < 0) ? q1.x : q1.z;
    uint32_t p11 = (qy0 < 0) ? ((qx0 < 0) ? q1.x : q1.y)
                             : ((qx0 < 0) ? q1.z : q1.w);

    // feat1: FMA accumulation (within ~1e-7 of reference order; tol 1e-3).
    float ff[8];
#pragma unroll
    for (int c = 0; c < 8; c++) {
        float s = dec(p00, c) * w00;
        s = fmaf(dec(p10, c), w10, s);
        s = fmaf(dec(p01, c), w01, s);
        s = fmaf(dec(p11, c), w11, s);
        ff[c] = s;
    }

    // Stage: raw g0 corner codes + decoded feat1 (3x STS.128 per point).
    uint4 q0 = make_uint4((uint32_t)e_top, (uint32_t)(e_top >> 32),
                          (uint32_t)e_bot, (uint32_t)(e_bot >> 32));
    float* s = &sbuf[warp * (32 * 12) + lane * 12];
    *(uint4*)s = q0;
    *(float4*)(s + 4) = make_float4(ff[0], ff[1], ff[2], ff[3]);
    *(float4*)(s + 8) = make_float4(ff[4], ff[5], ff[6], ff[7]);
    __syncwarp();

    // Coalesced readout: decode feat0 nibbles on the fly.
    const float* ws = &sbuf[warp * (32 * 12)];
    float4* go = reinterpret_cast<float4*>(out) +
                 (size_t)(blockIdx.x * 256 + warp * 32) * 10;
#pragma unroll
    for (int k = 0; k < 10; k++) {
        int wo = lane + 32 * k;        // float4 index within the warp's 320
        int pp = wo / 10;              // point within warp tile
        int jj = wo - pp * 10;         // float4 within point
        const float* sp = ws + pp * 12;
        float4 v;
        if (jj < 8) {
            uint32_t code = __float_as_uint(sp[jj >> 1]);  // corner jj>>1
            int cb = (jj & 1) * 4;
            v = make_float4(dec(code, cb), dec(code, cb + 1),
                            dec(code, cb + 2), dec(code, cb + 3));
        } else {
            v = *(const float4*)(sp + 4 + (jj - 8) * 4);   // staged feat1
        }
        __stcs(&go[wo], v);
    }
}

extern "C" void kernel_launch(void* const* d_in, const int* in_sizes, int n_in,
                              void* d_out, int out_size) {
    const float2* uv = (const float2*)d_in[0];
    const float*  g0 = (const float*)d_in[1];
    const float*  g1 = (const float*)d_in[2];

    pack_all<<<NBLK0 + NBLK1, 512>>>(g0, g1);
    sample_kernel<<<NPTS / 256, 256>>>(uv, (float*)d_out);
}